// round 1
// baseline (speedup 1.0000x reference)
#include <cuda_runtime.h>
#include <math.h>

#define BB 4
#define SEQ 577
#define DIMM 512
#define NH 8
#define NAA 4
#define MROWS (BB*SEQ)          /* 2308 */
#define QKVN (3*DIMM)           /* 1536 */
#define NN2 (SEQ*SEQ)           /* 332929 */
#define DOTSE (BB*NH*NN2)       /* 10653728 */
#define NROWS (BB*NH*SEQ)       /* 18464 */
#define SCALE_F 0.125f
#define PBB 512

// ---------------- scratch (static device globals; no allocation) ----------------
__device__ float g_qkv0[MROWS*QKVN];
__device__ float g_qkv1[MROWS*QKVN];
__device__ float g_dots0[DOTSE];
__device__ float g_dots1[DOTSE];
__device__ float g_ao0[MROWS*DIMM];
__device__ float g_ao1[MROWS*DIMM];
__device__ float g_rmax[2*NROWS];
__device__ float g_rsum[2*NROWS];
__device__ float g_bmax[2*BB];
__device__ float g_part[BB*PBB*3];

__device__ __forceinline__ void atomicMaxFloat(float* addr, float val){
    int* ai = (int*)addr;
    int old = *ai;
    while (__int_as_float(old) < val){
        int assumed = old;
        old = atomicCAS(ai, assumed, __float_as_int(val));
        if (old == assumed) break;
    }
}

__global__ void init_kernel(){
    int t = threadIdx.x;
    if (t < 2*BB) g_bmax[t] = -INFINITY;
}

// ---------------- generic fp32 GEMM body: C = A[M,K] @ W[K,N] + bias ----------------
// BM=128, BN=64, BK=16, 256 threads, 8x4 microtile
__device__ __forceinline__ void gemm_body(const float* __restrict__ A,
                                          const float* __restrict__ W,
                                          const float* __restrict__ bias,
                                          float* __restrict__ C,
                                          int M, int Nn, int K){
    __shared__ float As[16][132];
    __shared__ float Ws[16][68];
    const int tid = threadIdx.x;
    const int m0 = blockIdx.y * 128;
    const int n0 = blockIdx.x * 64;
    const int tx = tid & 15;
    const int ty = tid >> 4;
    float acc[8][4];
#pragma unroll
    for (int i=0;i<8;i++)
#pragma unroll
        for (int j=0;j<4;j++) acc[i][j]=0.f;

    for (int k0=0;k0<K;k0+=16){
#pragma unroll
        for (int t=0;t<8;t++){
            int idx = tid + t*256;
            int r = idx >> 4, c = idx & 15;
            int gr = m0 + r;
            As[c][r] = (gr < M) ? A[gr*K + k0 + c] : 0.f;
        }
#pragma unroll
        for (int t=0;t<4;t++){
            int idx = tid + t*256;
            int r = idx >> 6, c = idx & 63;
            Ws[r][c] = W[(k0+r)*Nn + n0 + c];
        }
        __syncthreads();
#pragma unroll
        for (int kk=0;kk<16;kk++){
            float a[8], w[4];
#pragma unroll
            for (int i=0;i<8;i++) a[i] = As[kk][ty*8+i];
#pragma unroll
            for (int j=0;j<4;j++) w[j] = Ws[kk][tx*4+j];
#pragma unroll
            for (int i=0;i<8;i++)
#pragma unroll
                for (int j=0;j<4;j++) acc[i][j] = fmaf(a[i], w[j], acc[i][j]);
        }
        __syncthreads();
    }
#pragma unroll
    for (int i=0;i<8;i++){
        int gr = m0 + ty*8 + i;
        if (gr < M){
#pragma unroll
            for (int j=0;j<4;j++){
                int gc = n0 + tx*4 + j;
                C[gr*Nn + gc] = acc[i][j] + bias[gc];
            }
        }
    }
}

__global__ void gemm_qkv_kernel(const float* __restrict__ x, const float* __restrict__ l,
                                const float* __restrict__ wqkv, const float* __restrict__ bqkv,
                                const float* __restrict__ wqkv1, const float* __restrict__ bqkv1){
    int s = blockIdx.z;
    gemm_body(s ? l : x, s ? wqkv1 : wqkv, s ? bqkv1 : bqkv,
              s ? g_qkv1 : g_qkv0, MROWS, QKVN, DIMM);
}

__global__ void gemm_mlp_kernel(const float* __restrict__ w_mlp, const float* __restrict__ b_mlp,
                                const float* __restrict__ w_mlp1, const float* __restrict__ b_mlp1,
                                float* __restrict__ out){
    int s = blockIdx.z;
    gemm_body(s ? g_ao1 : g_ao0, s ? w_mlp1 : w_mlp, s ? b_mlp1 : b_mlp,
              out + (size_t)s*MROWS*DIMM, MROWS, DIMM, DIMM);
}

// ---------------- dots + dots1 + fused sup + batch max ----------------
// per (b,h): dots = Q K^T * scale; sup = per-head tiny net; write dots+sup, dots1+sup
__global__ void dots_sup_kernel(const float* __restrict__ c1w, const float* __restrict__ c1b,
                                const float* __restrict__ bn_g, const float* __restrict__ bn_b,
                                const float* __restrict__ bn_m, const float* __restrict__ bn_v,
                                const float* __restrict__ c2w, const float* __restrict__ c2b){
    __shared__ float Qs0[16][65], Qs1[16][65], Ks0[16][65], Ks1[16][65];
    __shared__ float red0[8], red1[8];
    const int tid = threadIdx.x;
    const int bh = blockIdx.z;
    const int b = bh >> 3, h = bh & 7;
    const int i0 = blockIdx.y * 64, j0 = blockIdx.x * 64;
    const int tx = tid & 15, ty = tid >> 4;

    const float* q0p = g_qkv0 + b*SEQ*QKVN + h*64;
    const float* k0p = q0p + DIMM;
    const float* q1p = g_qkv1 + b*SEQ*QKVN + h*64;
    const float* k1p = q1p + DIMM;

    float a0[4][4], a1[4][4];
#pragma unroll
    for (int i=0;i<4;i++)
#pragma unroll
        for (int j=0;j<4;j++){ a0[i][j]=0.f; a1[i][j]=0.f; }

    for (int c0=0;c0<64;c0+=16){
#pragma unroll
        for (int t=0;t<4;t++){
            int idx = tid + t*256;
            int r = idx >> 4, c = idx & 15;
            int gi = i0 + r, gj = j0 + r;
            Qs0[c][r] = (gi<SEQ) ? q0p[gi*QKVN + c0 + c] : 0.f;
            Qs1[c][r] = (gi<SEQ) ? q1p[gi*QKVN + c0 + c] : 0.f;
            Ks0[c][r] = (gj<SEQ) ? k0p[gj*QKVN + c0 + c] : 0.f;
            Ks1[c][r] = (gj<SEQ) ? k1p[gj*QKVN + c0 + c] : 0.f;
        }
        __syncthreads();
#pragma unroll
        for (int kk=0;kk<16;kk++){
            float qa0[4],qa1[4],kb0[4],kb1[4];
#pragma unroll
            for (int i=0;i<4;i++){ qa0[i]=Qs0[kk][ty*4+i]; qa1[i]=Qs1[kk][ty*4+i]; }
#pragma unroll
            for (int j=0;j<4;j++){ kb0[j]=Ks0[kk][tx*4+j]; kb1[j]=Ks1[kk][tx*4+j]; }
#pragma unroll
            for (int i=0;i<4;i++)
#pragma unroll
                for (int j=0;j<4;j++){
                    a0[i][j] = fmaf(qa0[i], kb0[j], a0[i][j]);
                    a1[i][j] = fmaf(qa1[i], kb1[j], a1[i][j]);
                }
        }
        __syncthreads();
    }

    // per-head fused conv->BN->leaky->conv coefficients
    float Ao[NAA], Bo[NAA], Co[NAA], Wo[NAA];
#pragma unroll
    for (int o=0;o<NAA;o++){
        int idx = h*NAA + o;
        float inv = rsqrtf(bn_v[idx] + 1e-5f) * bn_g[idx];
        Ao[o] = c1w[idx*2]   * inv;
        Bo[o] = c1w[idx*2+1] * inv;
        Co[o] = (c1b[idx] - bn_m[idx]) * inv + bn_b[idx];
        Wo[o] = c2w[idx];
    }
    float c2bh = c2b[h];

    float lm0 = -INFINITY, lm1 = -INFINITY;
    const int rbase = bh*SEQ;
#pragma unroll
    for (int i=0;i<4;i++){
        int gi = i0 + ty*4 + i;
        if (gi >= SEQ) continue;
#pragma unroll
        for (int j=0;j<4;j++){
            int gj = j0 + tx*4 + j;
            if (gj >= SEQ) continue;
            float d  = a0[i][j]*SCALE_F;
            float d1 = a1[i][j]*SCALE_F;
            float sup = c2bh;
#pragma unroll
            for (int o=0;o<NAA;o++){
                float t = fmaf(Ao[o], d, fmaf(Bo[o], d1, Co[o]));
                t = (t > 0.f) ? t : 0.01f*t;
                sup = fmaf(t, Wo[o], sup);
            }
            float fd = d + sup, fd1 = d1 + sup;
            int off = (rbase + gi)*SEQ + gj;
            g_dots0[off] = fd;
            g_dots1[off] = fd1;
            lm0 = fmaxf(lm0, fd);
            lm1 = fmaxf(lm1, fd1);
        }
    }
#pragma unroll
    for (int off=16; off; off>>=1){
        lm0 = fmaxf(lm0, __shfl_xor_sync(0xffffffffu, lm0, off));
        lm1 = fmaxf(lm1, __shfl_xor_sync(0xffffffffu, lm1, off));
    }
    int lane = tid & 31, warp = tid >> 5;
    if (lane==0){ red0[warp]=lm0; red1[warp]=lm1; }
    __syncthreads();
    if (tid==0){
        float m0v=red0[0], m1v=red1[0];
        for (int w=1;w<8;w++){ m0v=fmaxf(m0v,red0[w]); m1v=fmaxf(m1v,red1[w]); }
        atomicMaxFloat(&g_bmax[b],    m0v);
        atomicMaxFloat(&g_bmax[BB+b], m1v);
    }
}

// ---------------- per-row softmax stats (one warp per row) ----------------
__global__ void rowstat_kernel(){
    int gtid = blockIdx.x*blockDim.x + threadIdx.x;
    int gw = gtid >> 5;
    int lane = gtid & 31;
    if (gw >= 2*NROWS) return;
    int s = gw / NROWS;
    int rr = gw - s*NROWS;
    const float* p = (s ? g_dots1 : g_dots0) + rr*SEQ;
    float v[19];
    float m = -INFINITY;
#pragma unroll
    for (int t=0;t<19;t++){
        int j = lane + t*32;
        v[t] = (j < SEQ) ? p[j] : -INFINITY;
        m = fmaxf(m, v[t]);
    }
#pragma unroll
    for (int off=16; off; off>>=1) m = fmaxf(m, __shfl_xor_sync(0xffffffffu, m, off));
    float sum = 0.f;
#pragma unroll
    for (int t=0;t<19;t++) sum += __expf(v[t] - m);
#pragma unroll
    for (int off=16; off; off>>=1) sum += __shfl_xor_sync(0xffffffffu, sum, off);
    if (lane==0){ g_rmax[gw]=m; g_rsum[gw]=sum; }
}

// ---------------- KL pieces: Z0, Z1, S partials (fixed grid -> deterministic) ----------------
__global__ void passB_kernel(){
    const int b = blockIdx.y;
    const float m0 = g_bmax[b], m1 = g_bmax[BB+b];
    const float* p0 = g_dots0 + b*NH*NN2;
    const float* p1 = g_dots1 + b*NH*NN2;
    const int total = NH*NN2;
    float z0=0.f, z1=0.f, sv=0.f;
    for (int idx = blockIdx.x*blockDim.x + threadIdx.x; idx < total; idx += PBB*256){
        float d = p0[idx], d1 = p1[idx];
        z0 += __expf(d - m0);
        float e1 = __expf(d1 - m1);
        z1 += e1;
        sv = fmaf(e1, d1 - d, sv);
    }
#pragma unroll
    for (int off=16; off; off>>=1){
        z0 += __shfl_xor_sync(0xffffffffu, z0, off);
        z1 += __shfl_xor_sync(0xffffffffu, z1, off);
        sv += __shfl_xor_sync(0xffffffffu, sv, off);
    }
    __shared__ float r0[8], r1[8], r2[8];
    int lane = threadIdx.x & 31, warp = threadIdx.x >> 5;
    if (lane==0){ r0[warp]=z0; r1[warp]=z1; r2[warp]=sv; }
    __syncthreads();
    if (threadIdx.x==0){
        float Z0=0,Z1=0,S=0;
        for (int w=0;w<8;w++){ Z0+=r0[w]; Z1+=r1[w]; S+=r2[w]; }
        int o = (b*PBB + blockIdx.x)*3;
        g_part[o]=Z0; g_part[o+1]=Z1; g_part[o+2]=S;
    }
}

__global__ void loss_kernel(float* __restrict__ out_loss){
    if (threadIdx.x!=0 || blockIdx.x!=0) return;
    float loss = 0.f;
    for (int b=0;b<BB;b++){
        float Z0=0,Z1=0,S=0;
        for (int k=0;k<PBB;k++){
            int o=(b*PBB+k)*3;
            Z0+=g_part[o]; Z1+=g_part[o+1]; S+=g_part[o+2];
        }
        loss += S/Z1 + (g_bmax[b] + logf(Z0)) - (g_bmax[BB+b] + logf(Z1));
    }
    *out_loss = loss * (1.0f/BB);
}

// ---------------- attn @ V with fused softmax normalization ----------------
// grid: (1, ceil(577/32)=19, 64= s*32 + b*8 + h); 32 rows x 64 (full D) per block
__global__ void attnv_kernel(){
    __shared__ float As[32][33];
    __shared__ float Vs[32][65];
    __shared__ float rm[32], rs[32];
    const int tid = threadIdx.x;
    const int z = blockIdx.z;
    const int s = z >> 5, bh = z & 31;
    const int b = bh >> 3, h = bh & 7;
    const int i0 = blockIdx.y * 32;
    const float* dots = (s ? g_dots1 : g_dots0) + bh*NN2;
    const float* vptr = (s ? g_qkv1 : g_qkv0) + b*SEQ*QKVN + 2*DIMM + h*64;
    float* ao = (s ? g_ao1 : g_ao0) + b*SEQ*DIMM + h*64;

    if (tid < 32){
        int gi = i0 + tid;
        int ri = s*NROWS + bh*SEQ + gi;
        rm[tid] = (gi<SEQ) ? g_rmax[ri] : 0.f;
        rs[tid] = (gi<SEQ) ? g_rsum[ri] : 1.f;
    }
    __syncthreads();

    const int tx = tid & 15, ty = tid >> 4;
    float acc[2][4] = {{0.f,0.f,0.f,0.f},{0.f,0.f,0.f,0.f}};

    for (int j0=0; j0<SEQ; j0+=32){
#pragma unroll
        for (int t=0;t<4;t++){
            int idx = tid + t*256;
            int i = idx >> 5, jj = idx & 31;
            int gi = i0+i, gj = j0+jj;
            float w = 0.f;
            if (gi < SEQ && gj < SEQ) w = __expf(dots[gi*SEQ+gj] - rm[i]);
            As[jj][i] = w;
        }
#pragma unroll
        for (int t=0;t<8;t++){
            int idx = tid + t*256;
            int jj = idx >> 6, dd = idx & 63;
            int gj = j0+jj;
            Vs[jj][dd] = (gj<SEQ) ? vptr[gj*QKVN + dd] : 0.f;
        }
        __syncthreads();
#pragma unroll
        for (int kk=0;kk<32;kk++){
            float av0 = As[kk][ty*2], av1 = As[kk][ty*2+1];
            float w4[4];
#pragma unroll
            for (int j=0;j<4;j++) w4[j] = Vs[kk][tx*4+j];
#pragma unroll
            for (int j=0;j<4;j++){
                acc[0][j] = fmaf(av0, w4[j], acc[0][j]);
                acc[1][j] = fmaf(av1, w4[j], acc[1][j]);
            }
        }
        __syncthreads();
    }
#pragma unroll
    for (int ii=0;ii<2;ii++){
        int gi = i0 + ty*2 + ii;
        if (gi < SEQ){
            float inv = 1.f / rs[ty*2+ii];
#pragma unroll
            for (int j=0;j<4;j++)
                ao[gi*DIMM + tx*4 + j] = acc[ii][j]*inv;
        }
    }
}

// ---------------- host launcher ----------------
extern "C" void kernel_launch(void* const* d_in, const int* in_sizes, int n_in,
                              void* d_out, int out_size){
    (void)in_sizes; (void)n_in; (void)out_size;
    const float* x     = (const float*)d_in[0];
    const float* l     = (const float*)d_in[1];
    /* d_in[2] = mask: unused by the module */
    const float* wqkv  = (const float*)d_in[3];
    const float* bqkv  = (const float*)d_in[4];
    const float* wqkv1 = (const float*)d_in[5];
    const float* bqkv1 = (const float*)d_in[6];
    const float* w_mlp  = (const float*)d_in[7];
    const float* b_mlp  = (const float*)d_in[8];
    const float* w_mlp1 = (const float*)d_in[9];
    const float* b_mlp1 = (const float*)d_in[10];
    const float* c1w  = (const float*)d_in[11];
    const float* c1b  = (const float*)d_in[12];
    const float* bn_g = (const float*)d_in[13];
    const float* bn_b = (const float*)d_in[14];
    const float* bn_m = (const float*)d_in[15];
    const float* bn_v = (const float*)d_in[16];
    const float* c2w  = (const float*)d_in[17];
    const float* c2b  = (const float*)d_in[18];
    float* out = (float*)d_out;

    init_kernel<<<1, 32>>>();
    gemm_qkv_kernel<<<dim3(QKVN/64, (MROWS+127)/128, 2), 256>>>(x, l, wqkv, bqkv, wqkv1, bqkv1);
    dots_sup_kernel<<<dim3(10, 10, BB*NH), 256>>>(c1w, c1b, bn_g, bn_b, bn_m, bn_v, c2w, c2b);
    rowstat_kernel<<<(2*NROWS*32 + 255)/256, 256>>>();
    passB_kernel<<<dim3(PBB, BB), 256>>>();
    loss_kernel<<<1, 32>>>(out + 2*(size_t)MROWS*DIMM);
    attnv_kernel<<<dim3(1, 19, 64), 256>>>();
    gemm_mlp_kernel<<<dim3(DIMM/64, (MROWS+127)/128, 2), 256>>>(w_mlp, b_mlp, w_mlp1, b_mlp1, out);
}

// round 3
// speedup vs baseline: 1.3373x; 1.3373x over previous
#include <cuda_runtime.h>
#include <math.h>

#define BB 4
#define SEQ 577
#define DIMM 512
#define NH 8
#define NAA 4
#define MROWS (BB*SEQ)          /* 2308 */
#define QKVN (3*DIMM)           /* 1536 */
#define NN2 (SEQ*SEQ)           /* 332929 */
#define DOTSE (BB*NH*NN2)       /* 10653728 */
#define NROWS (BB*NH*SEQ)       /* 18464 */
#define SCALE_F 0.125f
#define PPB 577                 /* partial blocks per batch in rowkl */

// ---------------- scratch (static device globals; no allocation) ----------------
__device__ float g_qkv0[MROWS*QKVN];
__device__ float g_qkv1[MROWS*QKVN];
__device__ float g_dots0[DOTSE];
__device__ float g_dots1[DOTSE];
__device__ float g_ao0[MROWS*DIMM];
__device__ float g_ao1[MROWS*DIMM];
__device__ float g_rmax[2*NROWS];
__device__ float g_rsum[2*NROWS];
__device__ float g_bmax[2*BB];
__device__ float g_part[BB*PPB*3];

__device__ __forceinline__ void atomicMaxFloat(float* addr, float val){
    int* ai = (int*)addr;
    int old = *ai;
    while (__int_as_float(old) < val){
        int assumed = old;
        old = atomicCAS(ai, assumed, __float_as_int(val));
        if (old == assumed) break;
    }
}

__global__ void init_kernel(){
    int t = threadIdx.x;
    if (t < 2*BB) g_bmax[t] = -INFINITY;
}

// ---------------- fp32 GEMM: C = A[M,K] @ W[K,N] + bias ----------------
// BM=128, BN=128, BK=16, 256 threads, 8x8 microtile, lds.128 inner loop
__device__ __forceinline__ void gemm_body(const float* __restrict__ A,
                                          const float* __restrict__ W,
                                          const float* __restrict__ bias,
                                          float* __restrict__ C,
                                          int M, int Nn, int K){
    __shared__ float As[16][132];
    __shared__ float Ws[16][132];
    const int tid = threadIdx.x;
    const int m0 = blockIdx.y * 128;
    const int n0 = blockIdx.x * 128;
    const int tx = tid & 15;
    const int ty = tid >> 4;
    float acc[8][8];
#pragma unroll
    for (int i=0;i<8;i++)
#pragma unroll
        for (int j=0;j<8;j++) acc[i][j]=0.f;

    for (int k0=0;k0<K;k0+=16){
        // A tile 128x16 -> transposed As[k][m] (512 float4, 2 per thread)
#pragma unroll
        for (int s=0;s<2;s++){
            int idx = tid + s*256;
            int r = idx >> 2;
            int c = (idx & 3) * 4;
            int gr = m0 + r;
            float4 v = make_float4(0.f,0.f,0.f,0.f);
            if (gr < M) v = *reinterpret_cast<const float4*>(&A[(size_t)gr*K + k0 + c]);
            As[c+0][r]=v.x; As[c+1][r]=v.y; As[c+2][r]=v.z; As[c+3][r]=v.w;
        }
        // W tile 16x128 -> Ws[k][n] (512 float4, 2 per thread)
#pragma unroll
        for (int s=0;s<2;s++){
            int idx = tid + s*256;
            int r = idx >> 5;
            int c = (idx & 31) * 4;
            float4 v = *reinterpret_cast<const float4*>(&W[(size_t)(k0+r)*Nn + n0 + c]);
            *reinterpret_cast<float4*>(&Ws[r][c]) = v;
        }
        __syncthreads();
#pragma unroll
        for (int kk=0;kk<16;kk++){
            float4 a0 = *reinterpret_cast<const float4*>(&As[kk][ty*8]);
            float4 a1 = *reinterpret_cast<const float4*>(&As[kk][ty*8+4]);
            float4 b0 = *reinterpret_cast<const float4*>(&Ws[kk][tx*8]);
            float4 b1 = *reinterpret_cast<const float4*>(&Ws[kk][tx*8+4]);
            float a[8] = {a0.x,a0.y,a0.z,a0.w,a1.x,a1.y,a1.z,a1.w};
            float b[8] = {b0.x,b0.y,b0.z,b0.w,b1.x,b1.y,b1.z,b1.w};
#pragma unroll
            for (int i=0;i<8;i++)
#pragma unroll
                for (int j=0;j<8;j++) acc[i][j] = fmaf(a[i], b[j], acc[i][j]);
        }
        __syncthreads();
    }
    float bv[8];
#pragma unroll
    for (int j=0;j<8;j++) bv[j] = bias[n0 + tx*8 + j];
#pragma unroll
    for (int i=0;i<8;i++){
        int gr = m0 + ty*8 + i;
        if (gr < M){
            float4 o0 = make_float4(acc[i][0]+bv[0], acc[i][1]+bv[1], acc[i][2]+bv[2], acc[i][3]+bv[3]);
            float4 o1 = make_float4(acc[i][4]+bv[4], acc[i][5]+bv[5], acc[i][6]+bv[6], acc[i][7]+bv[7]);
            *reinterpret_cast<float4*>(&C[(size_t)gr*Nn + n0 + tx*8])     = o0;
            *reinterpret_cast<float4*>(&C[(size_t)gr*Nn + n0 + tx*8 + 4]) = o1;
        }
    }
}

__global__ void __launch_bounds__(256) gemm_qkv_kernel(
        const float* __restrict__ x, const float* __restrict__ l,
        const float* __restrict__ wqkv, const float* __restrict__ bqkv,
        const float* __restrict__ wqkv1, const float* __restrict__ bqkv1){
    int s = blockIdx.z;
    gemm_body(s ? l : x, s ? wqkv1 : wqkv, s ? bqkv1 : bqkv,
              s ? g_qkv1 : g_qkv0, MROWS, QKVN, DIMM);
}

__global__ void __launch_bounds__(256) gemm_mlp_kernel(
        const float* __restrict__ w_mlp, const float* __restrict__ b_mlp,
        const float* __restrict__ w_mlp1, const float* __restrict__ b_mlp1,
        float* __restrict__ out){
    int s = blockIdx.z;
    gemm_body(s ? g_ao1 : g_ao0, s ? w_mlp1 : w_mlp, s ? b_mlp1 : b_mlp,
              out + (size_t)s*MROWS*DIMM, MROWS, DIMM, DIMM);
}

// ---------------- dots + dots1 + fused sup + batch max ----------------
// 64x64 tile, both streams, 4x4 microtile each, lds.128 inner loop
__global__ void __launch_bounds__(256) dots_sup_kernel(
        const float* __restrict__ c1w, const float* __restrict__ c1b,
        const float* __restrict__ bn_g, const float* __restrict__ bn_b,
        const float* __restrict__ bn_m, const float* __restrict__ bn_v,
        const float* __restrict__ c2w, const float* __restrict__ c2b){
    __shared__ float Qs0[16][68], Qs1[16][68], Ks0[16][68], Ks1[16][68];
    __shared__ float red0[8], red1[8];
    const int tid = threadIdx.x;
    const int bh = blockIdx.z;
    const int b = bh >> 3, h = bh & 7;
    const int i0 = blockIdx.y * 64, j0 = blockIdx.x * 64;
    const int tx = tid & 15, ty = tid >> 4;

    const float* q0p = g_qkv0 + (size_t)b*SEQ*QKVN + h*64;
    const float* k0p = q0p + DIMM;
    const float* q1p = g_qkv1 + (size_t)b*SEQ*QKVN + h*64;
    const float* k1p = q1p + DIMM;

    float a0[4][4], a1[4][4];
#pragma unroll
    for (int i=0;i<4;i++)
#pragma unroll
        for (int j=0;j<4;j++){ a0[i][j]=0.f; a1[i][j]=0.f; }

    for (int c0=0;c0<64;c0+=16){
        // 64 rows x 16 cols per tile = 256 float4; one per thread per tile
        {
            int r = tid >> 2;
            int c = (tid & 3) * 4;
            int gi = i0 + r, gj = j0 + r;
            float4 vq0 = make_float4(0,0,0,0), vq1 = vq0, vk0 = vq0, vk1 = vq0;
            if (gi < SEQ){
                vq0 = *reinterpret_cast<const float4*>(&q0p[(size_t)gi*QKVN + c0 + c]);
                vq1 = *reinterpret_cast<const float4*>(&q1p[(size_t)gi*QKVN + c0 + c]);
            }
            if (gj < SEQ){
                vk0 = *reinterpret_cast<const float4*>(&k0p[(size_t)gj*QKVN + c0 + c]);
                vk1 = *reinterpret_cast<const float4*>(&k1p[(size_t)gj*QKVN + c0 + c]);
            }
            Qs0[c+0][r]=vq0.x; Qs0[c+1][r]=vq0.y; Qs0[c+2][r]=vq0.z; Qs0[c+3][r]=vq0.w;
            Qs1[c+0][r]=vq1.x; Qs1[c+1][r]=vq1.y; Qs1[c+2][r]=vq1.z; Qs1[c+3][r]=vq1.w;
            Ks0[c+0][r]=vk0.x; Ks0[c+1][r]=vk0.y; Ks0[c+2][r]=vk0.z; Ks0[c+3][r]=vk0.w;
            Ks1[c+0][r]=vk1.x; Ks1[c+1][r]=vk1.y; Ks1[c+2][r]=vk1.z; Ks1[c+3][r]=vk1.w;
        }
        __syncthreads();
#pragma unroll
        for (int kk=0;kk<16;kk++){
            float4 q0 = *reinterpret_cast<const float4*>(&Qs0[kk][ty*4]);
            float4 q1 = *reinterpret_cast<const float4*>(&Qs1[kk][ty*4]);
            float4 k0 = *reinterpret_cast<const float4*>(&Ks0[kk][tx*4]);
            float4 k1 = *reinterpret_cast<const float4*>(&Ks1[kk][tx*4]);
            float qa0[4]={q0.x,q0.y,q0.z,q0.w}, qa1[4]={q1.x,q1.y,q1.z,q1.w};
            float kb0[4]={k0.x,k0.y,k0.z,k0.w}, kb1[4]={k1.x,k1.y,k1.z,k1.w};
#pragma unroll
            for (int i=0;i<4;i++)
#pragma unroll
                for (int j=0;j<4;j++){
                    a0[i][j] = fmaf(qa0[i], kb0[j], a0[i][j]);
                    a1[i][j] = fmaf(qa1[i], kb1[j], a1[i][j]);
                }
        }
        __syncthreads();
    }

    // per-head fused conv->BN->leaky->conv coefficients
    float Ao[NAA], Bo[NAA], Co[NAA], Wo[NAA];
#pragma unroll
    for (int o=0;o<NAA;o++){
        int idx = h*NAA + o;
        float inv = rsqrtf(bn_v[idx] + 1e-5f) * bn_g[idx];
        Ao[o] = c1w[idx*2]   * inv;
        Bo[o] = c1w[idx*2+1] * inv;
        Co[o] = (c1b[idx] - bn_m[idx]) * inv + bn_b[idx];
        Wo[o] = c2w[idx];
    }
    float c2bh = c2b[h];

    float lm0 = -INFINITY, lm1 = -INFINITY;
    const size_t rbase = (size_t)bh*SEQ;
#pragma unroll
    for (int i=0;i<4;i++){
        int gi = i0 + ty*4 + i;
        if (gi >= SEQ) continue;
#pragma unroll
        for (int j=0;j<4;j++){
            int gj = j0 + tx*4 + j;
            if (gj >= SEQ) continue;
            float d  = a0[i][j]*SCALE_F;
            float d1 = a1[i][j]*SCALE_F;
            float sup = c2bh;
#pragma unroll
            for (int o=0;o<NAA;o++){
                float t = fmaf(Ao[o], d, fmaf(Bo[o], d1, Co[o]));
                t = (t > 0.f) ? t : 0.01f*t;
                sup = fmaf(t, Wo[o], sup);
            }
            float fd = d + sup, fd1 = d1 + sup;
            size_t off = (rbase + gi)*SEQ + gj;
            g_dots0[off] = fd;
            g_dots1[off] = fd1;
            lm0 = fmaxf(lm0, fd);
            lm1 = fmaxf(lm1, fd1);
        }
    }
#pragma unroll
    for (int off=16; off; off>>=1){
        lm0 = fmaxf(lm0, __shfl_xor_sync(0xffffffffu, lm0, off));
        lm1 = fmaxf(lm1, __shfl_xor_sync(0xffffffffu, lm1, off));
    }
    int lane = tid & 31, warp = tid >> 5;
    if (lane==0){ red0[warp]=lm0; red1[warp]=lm1; }
    __syncthreads();
    if (tid==0){
        float m0v=red0[0], m1v=red1[0];
        for (int w=1;w<8;w++){ m0v=fmaxf(m0v,red0[w]); m1v=fmaxf(m1v,red1[w]); }
        atomicMaxFloat(&g_bmax[b],    m0v);
        atomicMaxFloat(&g_bmax[BB+b], m1v);
    }
}

// ---------------- fused row softmax stats + KL partials ----------------
// 1 warp per row pair (dots0 row r + dots1 row r), 8 rows per block.
// Z0_row = s0 * exp(m0 - mb0); Z1_row = s1 * exp(m1 - mb1);
// S_row  = exp(m1 - mb1) * sum(exp(d1 - m1) * (d1 - d))
__global__ void __launch_bounds__(256) rowkl_kernel(){
    const int warp = threadIdx.x >> 5;
    const int lane = threadIdx.x & 31;
    const int row = blockIdx.x*8 + warp;          // 0..NROWS-1
    const int b = row / (NH*SEQ);
    const float* p0 = g_dots0 + (size_t)row*SEQ;
    const float* p1 = g_dots1 + (size_t)row*SEQ;

    float v0[19], v1[19];
    float m0 = -INFINITY, m1 = -INFINITY;
#pragma unroll
    for (int t=0;t<19;t++){
        int j = lane + t*32;
        bool ok = (j < SEQ);
        v0[t] = ok ? p0[j] : -INFINITY;
        v1[t] = ok ? p1[j] : -INFINITY;
        m0 = fmaxf(m0, v0[t]);
        m1 = fmaxf(m1, v1[t]);
    }
#pragma unroll
    for (int off=16; off; off>>=1){
        m0 = fmaxf(m0, __shfl_xor_sync(0xffffffffu, m0, off));
        m1 = fmaxf(m1, __shfl_xor_sync(0xffffffffu, m1, off));
    }
    float s0=0.f, s1=0.f, tacc=0.f;
#pragma unroll
    for (int t=0;t<19;t++){
        int j = lane + t*32;
        if (j < SEQ){
            s0 += __expf(v0[t] - m0);
            float e1 = __expf(v1[t] - m1);
            s1 += e1;
            tacc = fmaf(e1, v1[t] - v0[t], tacc);
        }
    }
#pragma unroll
    for (int off=16; off; off>>=1){
        s0 += __shfl_xor_sync(0xffffffffu, s0, off);
        s1 += __shfl_xor_sync(0xffffffffu, s1, off);
        tacc += __shfl_xor_sync(0xffffffffu, tacc, off);
    }
    __shared__ float rz0[8], rz1[8], rS[8];
    if (lane==0){
        g_rmax[row] = m0;         g_rsum[row] = s0;
        g_rmax[NROWS+row] = m1;   g_rsum[NROWS+row] = s1;
        float e0b = __expf(m0 - g_bmax[b]);
        float e1b = __expf(m1 - g_bmax[BB+b]);
        rz0[warp] = s0 * e0b;
        rz1[warp] = s1 * e1b;
        rS[warp]  = tacc * e1b;
    }
    __syncthreads();
    if (threadIdx.x==0){
        float Z0=0,Z1=0,S=0;
#pragma unroll
        for (int w=0;w<8;w++){ Z0+=rz0[w]; Z1+=rz1[w]; S+=rS[w]; }
        // block index within batch: blockIdx.x % PPB (4616 rows/batch / 8 rows/block = 577)
        int kb = blockIdx.x - b*PPB;
        int o = (b*PPB + kb)*3;
        g_part[o]=Z0; g_part[o+1]=Z1; g_part[o+2]=S;
    }
}

__global__ void loss_kernel(float* __restrict__ out_loss){
    __shared__ float sh[3][256];
    const int t = threadIdx.x;
    float total = 0.f;
    for (int b=0;b<BB;b++){
        float Z0=0,Z1=0,S=0;
        for (int k=t;k<PPB;k+=256){
            int o=(b*PPB+k)*3;
            Z0+=g_part[o]; Z1+=g_part[o+1]; S+=g_part[o+2];
        }
        sh[0][t]=Z0; sh[1][t]=Z1; sh[2][t]=S;
        __syncthreads();
        for (int off=128; off; off>>=1){
            if (t < off){
                sh[0][t]+=sh[0][t+off];
                sh[1][t]+=sh[1][t+off];
                sh[2][t]+=sh[2][t+off];
            }
            __syncthreads();
        }
        if (t==0){
            total += sh[2][0]/sh[1][0]
                   + (g_bmax[b] + logf(sh[0][0]))
                   - (g_bmax[BB+b] + logf(sh[1][0]));
        }
        __syncthreads();
    }
    if (t==0) *out_loss = total * (1.0f/BB);
}

// ---------------- attn @ V with fused softmax normalization ----------------
// 64 rows x 64 (full D) per block, 4x4 microtile, lds.128 inner loop
__global__ void __launch_bounds__(256) attnv_kernel(){
    __shared__ float As[16][68];
    __shared__ float Vs[16][68];
    __shared__ float rm[64], rs[64];
    const int tid = threadIdx.x;
    const int z = blockIdx.z;
    const int s = z >> 5, bh = z & 31;
    const int b = bh >> 3, h = bh & 7;
    const int i0 = blockIdx.y * 64;
    const float* dots = (s ? g_dots1 : g_dots0) + (size_t)bh*NN2;
    const float* vptr = (s ? g_qkv1 : g_qkv0) + (size_t)b*SEQ*QKVN + 2*DIMM + h*64;
    float* ao = (s ? g_ao1 : g_ao0) + (size_t)b*SEQ*DIMM + h*64;

    if (tid < 64){
        int gi = i0 + tid;
        int ri = s*NROWS + bh*SEQ + gi;
        rm[tid] = (gi<SEQ) ? g_rmax[ri] : 0.f;
        rs[tid] = (gi<SEQ) ? g_rsum[ri] : 1.f;
    }
    __syncthreads();

    const int tx = tid & 15, ty = tid >> 4;
    float acc[4][4];
#pragma unroll
    for (int i=0;i<4;i++)
#pragma unroll
        for (int j=0;j<4;j++) acc[i][j]=0.f;

    for (int j0=0; j0<SEQ; j0+=16){
        // As[jj][i] = exp(dots[i][j] - rm[i]) — 64 x 16 = 1024 scalars, 4/thread
#pragma unroll
        for (int t=0;t<4;t++){
            int idx = tid + t*256;
            int i = idx >> 4, jj = idx & 15;
            int gi = i0+i, gj = j0+jj;
            float w = 0.f;
            if (gi < SEQ && gj < SEQ) w = __expf(dots[(size_t)gi*SEQ+gj] - rm[i]);
            As[jj][i] = w;
        }
        // Vs[jj][d] — 16 x 64 = 256 float4, 1/thread
        {
            int jj = tid >> 4, d = (tid & 15)*4;
            int gj = j0 + jj;
            float4 v = make_float4(0,0,0,0);
            if (gj < SEQ) v = *reinterpret_cast<const float4*>(&vptr[(size_t)gj*QKVN + d]);
            *reinterpret_cast<float4*>(&Vs[jj][d]) = v;
        }
        __syncthreads();
#pragma unroll
        for (int kk=0;kk<16;kk++){
            float4 av = *reinterpret_cast<const float4*>(&As[kk][ty*4]);
            float4 vv = *reinterpret_cast<const float4*>(&Vs[kk][tx*4]);
            float a[4]={av.x,av.y,av.z,av.w};
            float w[4]={vv.x,vv.y,vv.z,vv.w};
#pragma unroll
            for (int i=0;i<4;i++)
#pragma unroll
                for (int j=0;j<4;j++) acc[i][j] = fmaf(a[i], w[j], acc[i][j]);
        }
        __syncthreads();
    }
#pragma unroll
    for (int i=0;i<4;i++){
        int gi = i0 + ty*4 + i;
        if (gi < SEQ){
            float inv = 1.f / rs[ty*4+i];
            float4 o = make_float4(acc[i][0]*inv, acc[i][1]*inv, acc[i][2]*inv, acc[i][3]*inv);
            *reinterpret_cast<float4*>(&ao[(size_t)gi*DIMM + tx*4]) = o;
        }
    }
}

// ---------------- host launcher ----------------
extern "C" void kernel_launch(void* const* d_in, const int* in_sizes, int n_in,
                              void* d_out, int out_size){
    (void)in_sizes; (void)n_in; (void)out_size;
    const float* x     = (const float*)d_in[0];
    const float* l     = (const float*)d_in[1];
    /* d_in[2] = mask: unused by the module */
    const float* wqkv  = (const float*)d_in[3];
    const float* bqkv  = (const float*)d_in[4];
    const float* wqkv1 = (const float*)d_in[5];
    const float* bqkv1 = (const float*)d_in[6];
    const float* w_mlp  = (const float*)d_in[7];
    const float* b_mlp  = (const float*)d_in[8];
    const float* w_mlp1 = (const float*)d_in[9];
    const float* b_mlp1 = (const float*)d_in[10];
    const float* c1w  = (const float*)d_in[11];
    const float* c1b  = (const float*)d_in[12];
    const float* bn_g = (const float*)d_in[13];
    const float* bn_b = (const float*)d_in[14];
    const float* bn_m = (const float*)d_in[15];
    const float* bn_v = (const float*)d_in[16];
    const float* c2w  = (const float*)d_in[17];
    const float* c2b  = (const float*)d_in[18];
    float* out = (float*)d_out;

    init_kernel<<<1, 32>>>();
    gemm_qkv_kernel<<<dim3(QKVN/128, (MROWS+127)/128, 2), 256>>>(x, l, wqkv, bqkv, wqkv1, bqkv1);
    dots_sup_kernel<<<dim3(10, 10, BB*NH), 256>>>(c1w, c1b, bn_g, bn_b, bn_m, bn_v, c2w, c2b);
    rowkl_kernel<<<NROWS/8, 256>>>();
    loss_kernel<<<1, 256>>>(out + 2*(size_t)MROWS*DIMM);
    attnv_kernel<<<dim3(1, 10, 64), 256>>>();
    gemm_mlp_kernel<<<dim3(DIMM/128, (MROWS+127)/128, 2), 256>>>(w_mlp, b_mlp, w_mlp1, b_mlp1, out);
}

// round 5
// speedup vs baseline: 2.6579x; 1.9875x over previous
#include <cuda_runtime.h>
#include <math.h>

#define BB 4
#define SEQ 577
#define DIMM 512
#define NH 8
#define NAA 4
#define MROWS (BB*SEQ)          /* 2308 */
#define QKVN (3*DIMM)           /* 1536 */
#define NN2 (SEQ*SEQ)           /* 332929 */
#define DOTSE (BB*NH*NN2)       /* 10653728 */
#define NROWS (BB*NH*SEQ)       /* 18464 */
#define SCALE_F 0.125f
#define PPB 577                 /* partial blocks per batch in rowkl */

// ---------------- scratch (static device globals; no allocation) ----------------
__device__ float g_qkv0[MROWS*QKVN];
__device__ float g_qkv1[MROWS*QKVN];
__device__ float g_dots0[DOTSE];
__device__ float g_dots1[DOTSE];
__device__ float g_ao0[MROWS*DIMM];
__device__ float g_ao1[MROWS*DIMM];
__device__ float g_rmax[2*NROWS];
__device__ float g_rsum[2*NROWS];
__device__ float g_bmax[2*BB];
__device__ float g_part[BB*PPB*3];

__device__ __forceinline__ void atomicMaxFloat(float* addr, float val){
    int* ai = (int*)addr;
    int old = *ai;
    while (__int_as_float(old) < val){
        int assumed = old;
        old = atomicCAS(ai, assumed, __float_as_int(val));
        if (old == assumed) break;
    }
}

__global__ void init_kernel(){
    int t = threadIdx.x;
    if (t < 2*BB) g_bmax[t] = -INFINITY;
}

// ---------------- tf32 helpers ----------------
__device__ __forceinline__ unsigned f2tf(float f){
    unsigned u; asm("cvt.rna.tf32.f32 %0, %1;" : "=r"(u) : "f"(f)); return u;
}
__device__ __forceinline__ void st4tf(unsigned* p, float4 v){
    p[0]=f2tf(v.x); p[1]=f2tf(v.y); p[2]=f2tf(v.z); p[3]=f2tf(v.w);
}
// D += A(16x8) * B(8x8), tf32 inputs, fp32 accum
__device__ __forceinline__ void mma8(float* c, unsigned a0, unsigned a1, unsigned a2, unsigned a3,
                                     unsigned b0, unsigned b1){
    asm("mma.sync.aligned.m16n8k8.row.col.f32.tf32.tf32.f32 "
        "{%0,%1,%2,%3},{%4,%5,%6,%7},{%8,%9},{%0,%1,%2,%3};"
        : "+f"(c[0]),"+f"(c[1]),"+f"(c[2]),"+f"(c[3])
        : "r"(a0),"r"(a1),"r"(a2),"r"(a3),"r"(b0),"r"(b1));
}

// ---------------- tf32 GEMM: C = A[M,K] @ W[K,N] + bias ----------------
// BM=128, BN=128, BK=16, 256 threads, 8 warps as 2x4, warp tile 64x32
__device__ __forceinline__ void gemm_tf32_body(const float* __restrict__ A,
                                               const float* __restrict__ W,
                                               const float* __restrict__ bias,
                                               float* __restrict__ C,
                                               int M, int Nn, int K){
    __shared__ unsigned As[128][20];
    __shared__ unsigned Ws[16][136];
    const int tid = threadIdx.x;
    const int lane = tid & 31, wrp = tid >> 5;
    const int wm = wrp >> 2, wn = wrp & 3;
    const int m0 = blockIdx.y * 128;
    const int n0 = blockIdx.x * 128;
    const int lr = lane >> 2, lc = lane & 3;

    float acc[4][4][4];
#pragma unroll
    for (int i=0;i<4;i++)
#pragma unroll
        for (int j=0;j<4;j++)
#pragma unroll
            for (int e=0;e<4;e++) acc[i][j][e]=0.f;

    for (int k0=0;k0<K;k0+=16){
#pragma unroll
        for (int s=0;s<2;s++){
            int idx = tid + s*256;
            int r = idx >> 2, c = (idx & 3) * 4;
            int gr = m0 + r;
            float4 v = make_float4(0.f,0.f,0.f,0.f);
            if (gr < M) v = *reinterpret_cast<const float4*>(&A[(size_t)gr*K + k0 + c]);
            st4tf(&As[r][c], v);
        }
#pragma unroll
        for (int s=0;s<2;s++){
            int idx = tid + s*256;
            int r = idx >> 5, c = (idx & 31) * 4;
            float4 v = *reinterpret_cast<const float4*>(&W[(size_t)(k0+r)*Nn + n0 + c]);
            st4tf(&Ws[r][c], v);
        }
        __syncthreads();
#pragma unroll
        for (int kk=0;kk<16;kk+=8){
            unsigned a[4][4], b[4][2];
#pragma unroll
            for (int mt=0;mt<4;mt++){
                int row = wm*64 + mt*16 + lr;
                a[mt][0]=As[row  ][kk+lc];   a[mt][1]=As[row+8][kk+lc];
                a[mt][2]=As[row  ][kk+lc+4]; a[mt][3]=As[row+8][kk+lc+4];
            }
#pragma unroll
            for (int nt=0;nt<4;nt++){
                int col = wn*32 + nt*8 + lr;
                b[nt][0]=Ws[kk+lc][col]; b[nt][1]=Ws[kk+lc+4][col];
            }
#pragma unroll
            for (int mt=0;mt<4;mt++)
#pragma unroll
                for (int nt=0;nt<4;nt++)
                    mma8(acc[mt][nt], a[mt][0],a[mt][1],a[mt][2],a[mt][3], b[nt][0],b[nt][1]);
        }
        __syncthreads();
    }
#pragma unroll
    for (int mt=0;mt<4;mt++){
        int r0 = m0 + wm*64 + mt*16 + lr;
#pragma unroll
        for (int nt=0;nt<4;nt++){
            int c0 = n0 + wn*32 + nt*8 + lc*2;
            float b0 = bias[c0], b1 = bias[c0+1];
            if (r0 < M){
                float2 o = make_float2(acc[mt][nt][0]+b0, acc[mt][nt][1]+b1);
                *reinterpret_cast<float2*>(&C[(size_t)r0*Nn + c0]) = o;
            }
            if (r0+8 < M){
                float2 o = make_float2(acc[mt][nt][2]+b0, acc[mt][nt][3]+b1);
                *reinterpret_cast<float2*>(&C[(size_t)(r0+8)*Nn + c0]) = o;
            }
        }
    }
}

__global__ void __launch_bounds__(256) gemm_qkv_kernel(
        const float* __restrict__ x, const float* __restrict__ l,
        const float* __restrict__ wqkv, const float* __restrict__ bqkv,
        const float* __restrict__ wqkv1, const float* __restrict__ bqkv1){
    int s = blockIdx.z;
    gemm_tf32_body(s ? l : x, s ? wqkv1 : wqkv, s ? bqkv1 : bqkv,
                   s ? g_qkv1 : g_qkv0, MROWS, QKVN, DIMM);
}

__global__ void __launch_bounds__(256) gemm_mlp_kernel(
        const float* __restrict__ w_mlp, const float* __restrict__ b_mlp,
        const float* __restrict__ w_mlp1, const float* __restrict__ b_mlp1,
        float* __restrict__ out){
    int s = blockIdx.z;
    gemm_tf32_body(s ? g_ao1 : g_ao0, s ? w_mlp1 : w_mlp, s ? b_mlp1 : b_mlp,
                   out + (size_t)s*MROWS*DIMM, MROWS, DIMM, DIMM);
}

// ---------------- dots + dots1 + fused sup + batch max (tf32 MMA) ----------------
// block tile 64(i) x 128(j) per (b,h); 8 warps as 2x4, warp tile 32x32, dual stream
__global__ void __launch_bounds__(256) dots_sup_kernel(
        const float* __restrict__ c1w, const float* __restrict__ c1b,
        const float* __restrict__ bn_g, const float* __restrict__ bn_b,
        const float* __restrict__ bn_m, const float* __restrict__ bn_v,
        const float* __restrict__ c2w, const float* __restrict__ c2b){
    __shared__ unsigned Qs[2][64][20];
    __shared__ unsigned Ks[2][128][20];
    __shared__ float red0[8], red1[8];
    const int tid = threadIdx.x;
    const int lane = tid & 31, wrp = tid >> 5;
    const int wm = wrp >> 2, wn = wrp & 3;
    const int lr = lane >> 2, lc = lane & 3;
    const int bh = blockIdx.z;
    const int b = bh >> 3, h = bh & 7;
    const int i0 = blockIdx.y * 64, j0 = blockIdx.x * 128;

    const float* qp0 = g_qkv0 + (size_t)b*SEQ*QKVN + h*64;
    const float* qp1 = g_qkv1 + (size_t)b*SEQ*QKVN + h*64;
    const float* kp0 = qp0 + DIMM;
    const float* kp1 = qp1 + DIMM;

    float acc[2][2][4][4];
#pragma unroll
    for (int s=0;s<2;s++)
#pragma unroll
        for (int mt=0;mt<2;mt++)
#pragma unroll
            for (int nt=0;nt<4;nt++)
#pragma unroll
                for (int e=0;e<4;e++) acc[s][mt][nt][e]=0.f;

    for (int c0=0;c0<64;c0+=16){
        {   // Q tiles: 64x16 per stream, 256 float4 each -> 1/thread/stream
            int r = tid >> 2, c = (tid & 3) * 4;
            int gi = i0 + r;
            float4 v0 = make_float4(0,0,0,0), v1 = v0;
            if (gi < SEQ){
                v0 = *reinterpret_cast<const float4*>(&qp0[(size_t)gi*QKVN + c0 + c]);
                v1 = *reinterpret_cast<const float4*>(&qp1[(size_t)gi*QKVN + c0 + c]);
            }
            st4tf(&Qs[0][r][c], v0);
            st4tf(&Qs[1][r][c], v1);
        }
#pragma unroll
        for (int t=0;t<2;t++){ // K tiles: 128x16 per stream, 512 float4 each -> 2/thread/stream
            int idx = tid + t*256;
            int r = idx >> 2, c = (idx & 3) * 4;
            int gj = j0 + r;
            float4 v0 = make_float4(0,0,0,0), v1 = v0;
            if (gj < SEQ){
                v0 = *reinterpret_cast<const float4*>(&kp0[(size_t)gj*QKVN + c0 + c]);
                v1 = *reinterpret_cast<const float4*>(&kp1[(size_t)gj*QKVN + c0 + c]);
            }
            st4tf(&Ks[0][r][c], v0);
            st4tf(&Ks[1][r][c], v1);
        }
        __syncthreads();
#pragma unroll
        for (int kk=0;kk<16;kk+=8){
            unsigned a[2][2][4], bb[2][4][2];
#pragma unroll
            for (int s=0;s<2;s++){
#pragma unroll
                for (int mt=0;mt<2;mt++){
                    int row = wm*32 + mt*16 + lr;
                    a[s][mt][0]=Qs[s][row  ][kk+lc];   a[s][mt][1]=Qs[s][row+8][kk+lc];
                    a[s][mt][2]=Qs[s][row  ][kk+lc+4]; a[s][mt][3]=Qs[s][row+8][kk+lc+4];
                }
#pragma unroll
                for (int nt=0;nt<4;nt++){
                    int col = wn*32 + nt*8 + lr;
                    bb[s][nt][0]=Ks[s][col][kk+lc]; bb[s][nt][1]=Ks[s][col][kk+lc+4];
                }
            }
#pragma unroll
            for (int s=0;s<2;s++)
#pragma unroll
                for (int mt=0;mt<2;mt++)
#pragma unroll
                    for (int nt=0;nt<4;nt++)
                        mma8(acc[s][mt][nt], a[s][mt][0],a[s][mt][1],a[s][mt][2],a[s][mt][3],
                             bb[s][nt][0],bb[s][nt][1]);
        }
        __syncthreads();
    }

    // per-head fused conv->BN->leaky->conv coefficients
    float Ao[NAA], Bo[NAA], Co[NAA], Wo[NAA];
#pragma unroll
    for (int o=0;o<NAA;o++){
        int idx = h*NAA + o;
        float inv = rsqrtf(bn_v[idx] + 1e-5f) * bn_g[idx];
        Ao[o] = c1w[idx*2]   * inv;
        Bo[o] = c1w[idx*2+1] * inv;
        Co[o] = (c1b[idx] - bn_m[idx]) * inv + bn_b[idx];
        Wo[o] = c2w[idx];
    }
    float c2bh = c2b[h];

    float lm0 = -INFINITY, lm1 = -INFINITY;
    const size_t rbase = (size_t)bh*SEQ;
#pragma unroll
    for (int mt=0;mt<2;mt++){
#pragma unroll
        for (int half=0;half<2;half++){
            int row = i0 + wm*32 + mt*16 + lr + half*8;
            if (row >= SEQ) continue;
#pragma unroll
            for (int nt=0;nt<4;nt++){
                int c0 = j0 + wn*32 + nt*8 + lc*2;
                // NOTE: scalar stores only — row*SEQ is odd for odd rows (SEQ=577),
                // so 8B vector stores to g_dots would be misaligned.
#pragma unroll
                for (int e=0;e<2;e++){
                    int gj = c0 + e;
                    if (gj >= SEQ) continue;
                    float d  = acc[0][mt][nt][half*2+e]*SCALE_F;
                    float d1 = acc[1][mt][nt][half*2+e]*SCALE_F;
                    float sup = c2bh;
#pragma unroll
                    for (int o=0;o<NAA;o++){
                        float t = fmaf(Ao[o], d, fmaf(Bo[o], d1, Co[o]));
                        t = (t > 0.f) ? t : 0.01f*t;
                        sup = fmaf(t, Wo[o], sup);
                    }
                    float fd = d + sup, fd1 = d1 + sup;
                    size_t off = (rbase + row)*SEQ + gj;
                    g_dots0[off] = fd;
                    g_dots1[off] = fd1;
                    lm0 = fmaxf(lm0, fd);
                    lm1 = fmaxf(lm1, fd1);
                }
            }
        }
    }
#pragma unroll
    for (int off=16; off; off>>=1){
        lm0 = fmaxf(lm0, __shfl_xor_sync(0xffffffffu, lm0, off));
        lm1 = fmaxf(lm1, __shfl_xor_sync(0xffffffffu, lm1, off));
    }
    if (lane==0){ red0[wrp]=lm0; red1[wrp]=lm1; }
    __syncthreads();
    if (tid==0){
        float m0v=red0[0], m1v=red1[0];
        for (int w2=1;w2<8;w2++){ m0v=fmaxf(m0v,red0[w2]); m1v=fmaxf(m1v,red1[w2]); }
        atomicMaxFloat(&g_bmax[b],    m0v);
        atomicMaxFloat(&g_bmax[BB+b], m1v);
    }
}

// ---------------- fused row softmax stats + KL partials ----------------
__global__ void __launch_bounds__(256) rowkl_kernel(){
    const int warp = threadIdx.x >> 5;
    const int lane = threadIdx.x & 31;
    const int row = blockIdx.x*8 + warp;          // 0..NROWS-1
    const int b = row / (NH*SEQ);
    const float* p0 = g_dots0 + (size_t)row*SEQ;
    const float* p1 = g_dots1 + (size_t)row*SEQ;

    float v0[19], v1[19];
    float m0 = -INFINITY, m1 = -INFINITY;
#pragma unroll
    for (int t=0;t<19;t++){
        int j = lane + t*32;
        bool ok = (j < SEQ);
        v0[t] = ok ? p0[j] : -INFINITY;
        v1[t] = ok ? p1[j] : -INFINITY;
        m0 = fmaxf(m0, v0[t]);
        m1 = fmaxf(m1, v1[t]);
    }
#pragma unroll
    for (int off=16; off; off>>=1){
        m0 = fmaxf(m0, __shfl_xor_sync(0xffffffffu, m0, off));
        m1 = fmaxf(m1, __shfl_xor_sync(0xffffffffu, m1, off));
    }
    float s0=0.f, s1=0.f, tacc=0.f;
#pragma unroll
    for (int t=0;t<19;t++){
        int j = lane + t*32;
        if (j < SEQ){
            s0 += __expf(v0[t] - m0);
            float e1 = __expf(v1[t] - m1);
            s1 += e1;
            tacc = fmaf(e1, v1[t] - v0[t], tacc);
        }
    }
#pragma unroll
    for (int off=16; off; off>>=1){
        s0 += __shfl_xor_sync(0xffffffffu, s0, off);
        s1 += __shfl_xor_sync(0xffffffffu, s1, off);
        tacc += __shfl_xor_sync(0xffffffffu, tacc, off);
    }
    __shared__ float rz0[8], rz1[8], rS[8];
    if (lane==0){
        g_rmax[row] = m0;         g_rsum[row] = s0;
        g_rmax[NROWS+row] = m1;   g_rsum[NROWS+row] = s1;
        float e0b = __expf(m0 - g_bmax[b]);
        float e1b = __expf(m1 - g_bmax[BB+b]);
        rz0[warp] = s0 * e0b;
        rz1[warp] = s1 * e1b;
        rS[warp]  = tacc * e1b;
    }
    __syncthreads();
    if (threadIdx.x==0){
        float Z0=0,Z1=0,S=0;
#pragma unroll
        for (int w=0;w<8;w++){ Z0+=rz0[w]; Z1+=rz1[w]; S+=rS[w]; }
        int kb = blockIdx.x - b*PPB;
        int o = (b*PPB + kb)*3;
        g_part[o]=Z0; g_part[o+1]=Z1; g_part[o+2]=S;
    }
}

__global__ void loss_kernel(float* __restrict__ out_loss){
    __shared__ float sh[3][256];
    const int t = threadIdx.x;
    float total = 0.f;
    for (int b=0;b<BB;b++){
        float Z0=0,Z1=0,S=0;
        for (int k=t;k<PPB;k+=256){
            int o=(b*PPB+k)*3;
            Z0+=g_part[o]; Z1+=g_part[o+1]; S+=g_part[o+2];
        }
        sh[0][t]=Z0; sh[1][t]=Z1; sh[2][t]=S;
        __syncthreads();
        for (int off=128; off; off>>=1){
            if (t < off){
                sh[0][t]+=sh[0][t+off];
                sh[1][t]+=sh[1][t+off];
                sh[2][t]+=sh[2][t+off];
            }
            __syncthreads();
        }
        if (t==0){
            total += sh[2][0]/sh[1][0]
                   + (g_bmax[b] + logf(sh[0][0]))
                   - (g_bmax[BB+b] + logf(sh[1][0]));
        }
        __syncthreads();
    }
    if (t==0) *out_loss = total * (1.0f/BB);
}

// ---------------- attn @ V, tf32 MMA, fused softmax normalization ----------------
// block tile 64(i) x 64(d) per (s,bh); 8 warps as 2x4, warp tile 32x16; K-chunk 32
__global__ void __launch_bounds__(256) attnv_kernel(){
    __shared__ unsigned Es[64][36];
    __shared__ unsigned Vs[32][72];
    __shared__ float rm[64], rs[64];
    const int tid = threadIdx.x;
    const int lane = tid & 31, wrp = tid >> 5;
    const int wm = wrp >> 2, wn = wrp & 3;
    const int lr = lane >> 2, lc = lane & 3;
    const int z = blockIdx.z;
    const int s = z >> 5, bh = z & 31;
    const int b = bh >> 3, h = bh & 7;
    const int i0 = blockIdx.y * 64;
    const float* dots = (s ? g_dots1 : g_dots0) + (size_t)bh*NN2;
    const float* vptr = (s ? g_qkv1 : g_qkv0) + (size_t)b*SEQ*QKVN + 2*DIMM + h*64;
    float* ao = (s ? g_ao1 : g_ao0) + (size_t)b*SEQ*DIMM + h*64;

    if (tid < 64){
        int gi = i0 + tid;
        int ri = s*NROWS + bh*SEQ + gi;
        rm[tid] = (gi<SEQ) ? g_rmax[ri] : 0.f;
        rs[tid] = (gi<SEQ) ? g_rsum[ri] : 1.f;
    }
    __syncthreads();

    float acc[2][2][4];
#pragma unroll
    for (int mt=0;mt<2;mt++)
#pragma unroll
        for (int nt=0;nt<2;nt++)
#pragma unroll
            for (int e=0;e<4;e++) acc[mt][nt][e]=0.f;

    for (int j0=0; j0<SEQ; j0+=32){
#pragma unroll
        for (int t=0;t<8;t++){   // Es: 64x32 exps, 8/thread
            int idx = tid + t*256;
            int i = idx >> 5, j = idx & 31;
            int gi = i0+i, gj = j0+j;
            float w = 0.f;
            if (gi < SEQ && gj < SEQ) w = __expf(dots[(size_t)gi*SEQ+gj] - rm[i]);
            Es[i][j] = f2tf(w);
        }
#pragma unroll
        for (int t=0;t<2;t++){   // Vs: 32x64, 512 float4, 2/thread
            int idx = tid + t*256;
            int j = idx >> 4, c = (idx & 15)*4;
            int gj = j0 + j;
            float4 v = make_float4(0,0,0,0);
            if (gj < SEQ) v = *reinterpret_cast<const float4*>(&vptr[(size_t)gj*QKVN + c]);
            st4tf(&Vs[j][c], v);
        }
        __syncthreads();
#pragma unroll
        for (int kk=0;kk<32;kk+=8){
            unsigned a[2][4], bf[2][2];
#pragma unroll
            for (int mt=0;mt<2;mt++){
                int row = wm*32 + mt*16 + lr;
                a[mt][0]=Es[row  ][kk+lc];   a[mt][1]=Es[row+8][kk+lc];
                a[mt][2]=Es[row  ][kk+lc+4]; a[mt][3]=Es[row+8][kk+lc+4];
            }
#pragma unroll
            for (int nt=0;nt<2;nt++){
                int col = wn*16 + nt*8 + lr;
                bf[nt][0]=Vs[kk+lc][col]; bf[nt][1]=Vs[kk+lc+4][col];
            }
#pragma unroll
            for (int mt=0;mt<2;mt++)
#pragma unroll
                for (int nt=0;nt<2;nt++)
                    mma8(acc[mt][nt], a[mt][0],a[mt][1],a[mt][2],a[mt][3], bf[nt][0],bf[nt][1]);
        }
        __syncthreads();
    }
#pragma unroll
    for (int mt=0;mt<2;mt++){
        int lrow = wm*32 + mt*16 + lr;
        int r0 = i0 + lrow;
#pragma unroll
        for (int nt=0;nt<2;nt++){
            int c0 = wn*16 + nt*8 + lc*2;
            if (r0 < SEQ){
                float inv = 1.f / rs[lrow];
                float2 o = make_float2(acc[mt][nt][0]*inv, acc[mt][nt][1]*inv);
                *reinterpret_cast<float2*>(&ao[(size_t)r0*DIMM + c0]) = o;
            }
            if (r0+8 < SEQ){
                float inv = 1.f / rs[lrow+8];
                float2 o = make_float2(acc[mt][nt][2]*inv, acc[mt][nt][3]*inv);
                *reinterpret_cast<float2*>(&ao[(size_t)(r0+8)*DIMM + c0]) = o;
            }
        }
    }
}

// ---------------- host launcher ----------------
extern "C" void kernel_launch(void* const* d_in, const int* in_sizes, int n_in,
                              void* d_out, int out_size){
    (void)in_sizes; (void)n_in; (void)out_size;
    const float* x     = (const float*)d_in[0];
    const float* l     = (const float*)d_in[1];
    /* d_in[2] = mask: unused by the module */
    const float* wqkv  = (const float*)d_in[3];
    const float* bqkv  = (const float*)d_in[4];
    const float* wqkv1 = (const float*)d_in[5];
    const float* bqkv1 = (const float*)d_in[6];
    const float* w_mlp  = (const float*)d_in[7];
    const float* b_mlp  = (const float*)d_in[8];
    const float* w_mlp1 = (const float*)d_in[9];
    const float* b_mlp1 = (const float*)d_in[10];
    const float* c1w  = (const float*)d_in[11];
    const float* c1b  = (const float*)d_in[12];
    const float* bn_g = (const float*)d_in[13];
    const float* bn_b = (const float*)d_in[14];
    const float* bn_m = (const float*)d_in[15];
    const float* bn_v = (const float*)d_in[16];
    const float* c2w  = (const float*)d_in[17];
    const float* c2b  = (const float*)d_in[18];
    float* out = (float*)d_out;

    init_kernel<<<1, 32>>>();
    gemm_qkv_kernel<<<dim3(QKVN/128, (MROWS+127)/128, 2), 256>>>(x, l, wqkv, bqkv, wqkv1, bqkv1);
    dots_sup_kernel<<<dim3(5, 10, BB*NH), 256>>>(c1w, c1b, bn_g, bn_b, bn_m, bn_v, c2w, c2b);
    rowkl_kernel<<<NROWS/8, 256>>>();
    loss_kernel<<<1, 256>>>(out + 2*(size_t)MROWS*DIMM);
    attnv_kernel<<<dim3(1, 10, 64), 256>>>();
    gemm_mlp_kernel<<<dim3(DIMM/128, (MROWS+127)/128, 2), 256>>>(w_mlp, b_mlp, w_mlp1, b_mlp1, out);
}